// round 7
// baseline (speedup 1.0000x reference)
#include <cuda_runtime.h>
#include <cuda_bf16.h>
#include <cstdint>

// ---------------------------------------------------------------------------
// FNO spectral block: B=2, H=1024, W=1024, C=32, modes rows {0..31,992..1023},
// cols 0..31.  Factored into 4 partial-DFT GEMM stages, fp32 with f32x2 FMA.
// ---------------------------------------------------------------------------

#define Bn 2
#define Hn 1024
#define Wn 1024
#define Cn 32

// ---- device scratch (allocation-free) ----
__device__ float g_FAT[64 * 1024];                  // [fcol][w]: fcol=2k2 -> cos, 2k2+1 -> -sin
__device__ float g_GD [1024 * 64];                  // [w][fcol]: sc*cos, -sc*sin
__device__ float g_EB4[1024 * 64 * 4];              // [h][k1i]: (c,-s, s,c)   e^{-i th}
__device__ float g_EC4[1024 * 64 * 4];              // [h][k1i]: (c, s,-s,c)/H e^{+i th}/H
__device__ float g_Wc [32 * 64 * 32 * 2];           // combined w0*(w1|w2), complex
__device__ float g_A  [(size_t)Bn * Cn * Hn * 64];  // [b][c][h][fcol]
__device__ float g_Xp [8 * 32 * 64 * 32 * 2];       // [hq*2+b][c][k1i][k2] complex partials
__device__ float g_XW [(size_t)Bn * Cn * 64 * 64];  // [b][c][k1i][2k2]
__device__ float g_Z  [(size_t)Bn * Hn * Cn * 64];  // [b][h][c][fcol]

// ---- packed fp32x2 helpers (Blackwell f32x2 pipe) ----
__device__ __forceinline__ void fma2(unsigned long long& acc,
                                     unsigned long long a,
                                     unsigned long long b) {
    asm("fma.rn.f32x2 %0, %1, %2, %0;" : "+l"(acc) : "l"(a), "l"(b));
}
__device__ __forceinline__ unsigned long long pack2(float x, float y) {
    unsigned long long r;
    asm("mov.b64 %0, {%1, %2};" : "=l"(r) : "f"(x), "f"(y));
    return r;
}
__device__ __forceinline__ float2 unpack2(unsigned long long v) {
    float2 r;
    asm("mov.b64 {%0, %1}, %2;" : "=f"(r.x), "=f"(r.y) : "l"(v));
    return r;
}

// ---------------------------------------------------------------------------
// Twiddle tables.  Exact integer mod-1024 phase + double sincospi.
// ---------------------------------------------------------------------------
__global__ void k_init_tables() {
    const int row = blockIdx.x;     // w for FAT/GD, h for EB4/EC4
    const int t = threadIdx.x;      // 64
    if (t < 32) {
        const int k2 = t;
        const int r = (k2 * row) & 1023;
        double s, c;
        sincospi((double)r / 512.0, &s, &c);
        g_FAT[(2 * k2)     * 1024 + row] = (float)c;
        g_FAT[(2 * k2 + 1) * 1024 + row] = (float)(-s);
        const double sc = (k2 == 0 ? 1.0 : 2.0) / 1024.0;
        g_GD[row * 64 + 2 * k2]     = (float)(sc * c);
        g_GD[row * 64 + 2 * k2 + 1] = (float)(-sc * s);
    }
    {
        const int k1i = t;
        const int k1 = (k1i < 32) ? k1i : (960 + k1i);  // 992..1023
        const int r = (k1 * row) & 1023;
        double s, c;
        sincospi((double)r / 512.0, &s, &c);
        float* eb = &g_EB4[(row * 64 + k1i) * 4];
        eb[0] = (float)c;  eb[1] = (float)(-s);
        eb[2] = (float)s;  eb[3] = (float)c;
        const double inv = 1.0 / 1024.0;
        float* ec = &g_EC4[(row * 64 + k1i) * 4];
        ec[0] = (float)(c * inv);  ec[1] = (float)(s * inv);
        ec[2] = (float)(-s * inv); ec[3] = (float)(c * inv);
    }
}

// Combined weights Wc[c][k1i][k2] = w0[c] * (w1|w2)[c, m1, k2], complex.
__global__ void k_init_w(const float* __restrict__ w0r, const float* __restrict__ w0i,
                         const float* __restrict__ w1r, const float* __restrict__ w1i,
                         const float* __restrict__ w2r, const float* __restrict__ w2i) {
    const int idx = blockIdx.x * 256 + threadIdx.x;   // 65536
    const int k2 = idx & 31;
    const int k1i = (idx >> 5) & 63;
    const int c = idx >> 11;
    const float ar = w0r[c], ai = w0i[c];
    float br, bi;
    if (k1i < 32) {
        const int o = (c * 32 + k1i) * 32 + k2;
        br = w1r[o]; bi = w1i[o];
    } else {
        const int o = (c * 32 + (k1i - 32)) * 32 + k2;
        br = w2r[o]; bi = w2i[o];
    }
    g_Wc[idx * 2]     = ar * br - ai * bi;
    g_Wc[idx * 2 + 1] = ar * bi + ai * br;
}

// ---------------------------------------------------------------------------
// Stage A: A[b,c,h,fcol] = sum_w x[b,h,w,c] * FAT[fcol,w].
// CTA per (h,b).  M=32(c) x N=64(fcol) x K=1024(w), K-chunks of 64.
// Thread: 4 c x 2 fcol, f32x2 packs even/odd-w partial sums.
// ---------------------------------------------------------------------------
__global__ void __launch_bounds__(256) kA(const float* __restrict__ x) {
    const int h = blockIdx.x, b = blockIdx.y;
    __shared__ __align__(16) float xs[32 * 66];    // [c][w]
    __shared__ __align__(16) float FAs[64 * 66];   // [fcol][w]
    const int t = threadIdx.x;
    const int cg = (t & 7) * 4;
    const int fg = (t >> 3) * 2;
    unsigned long long acc[4][2] = {};
    const float* xrow = x + ((size_t)(b * 1024 + h)) * 1024 * 32;

    for (int w0 = 0; w0 < 1024; w0 += 64) {
        // xs: transpose-load 64w x 32c
#pragma unroll
        for (int k = 0; k < 2; k++) {
            const int idx = t + k * 256;             // 512 float4
            const int ww = idx >> 3, c4 = (idx & 7) * 4;
            const float4 v = *(const float4*)&xrow[(w0 + ww) * 32 + c4];
            xs[(c4 + 0) * 66 + ww] = v.x;
            xs[(c4 + 1) * 66 + ww] = v.y;
            xs[(c4 + 2) * 66 + ww] = v.z;
            xs[(c4 + 3) * 66 + ww] = v.w;
        }
        // FAs: 64 rows x 32 float2
#pragma unroll
        for (int k = 0; k < 8; k++) {
            const int idx = t + k * 256;             // 2048 float2
            const int fr = idx >> 5, wp2 = (idx & 31) * 2;
            *(float2*)&FAs[fr * 66 + wp2] = *(const float2*)&g_FAT[fr * 1024 + w0 + wp2];
        }
        __syncthreads();
#pragma unroll 8
        for (int wp = 0; wp < 32; wp++) {
            const unsigned long long fv0 = *(const unsigned long long*)&FAs[fg * 66 + 2 * wp];
            const unsigned long long fv1 = *(const unsigned long long*)&FAs[(fg + 1) * 66 + 2 * wp];
#pragma unroll
            for (int i = 0; i < 4; i++) {
                const unsigned long long xv = *(const unsigned long long*)&xs[(cg + i) * 66 + 2 * wp];
                fma2(acc[i][0], xv, fv0);
                fma2(acc[i][1], xv, fv1);
            }
        }
        __syncthreads();
    }
#pragma unroll
    for (int i = 0; i < 4; i++) {
        const float2 r0 = unpack2(acc[i][0]);
        const float2 r1 = unpack2(acc[i][1]);
        const float2 v = make_float2(r0.x + r0.y, r1.x + r1.y);
        *(float2*)&g_A[(((size_t)b * 32 + cg + i) * 1024 + h) * 64 + fg] = v;
    }
}

// ---------------------------------------------------------------------------
// Stage B: partial X over a 256-h quarter.
// CTA per (hq,c,b).  X[k1i,k2] += A[h,k2] * e^{-2pi i k1 h / 1024}.
// Thread: k2 = t&31, 8 consecutive k1i.  acc packs (Xr,Xi).
// ---------------------------------------------------------------------------
__global__ void __launch_bounds__(256) kB() {
    const int hq = blockIdx.x, c = blockIdx.y, b = blockIdx.z;
    __shared__ __align__(16) float As[32 * 66];
    __shared__ __align__(16) float EB4s[32 * 256];
    const int t = threadIdx.x;
    const int k2 = t & 31, r = t >> 5;
    unsigned long long acc[8] = {};
    const float* abase = g_A + ((size_t)(b * 32 + c) * 1024 + hq * 256) * 64;

    for (int ch = 0; ch < 8; ch++) {
        const int h0c = hq * 256 + ch * 32;
#pragma unroll
        for (int k = 0; k < 4; k++) {                // 1024 float2
            const int idx = t + k * 256;
            const int row = idx >> 5, cp = (idx & 31) * 2;
            *(float2*)&As[row * 66 + cp] = *(const float2*)&abase[(ch * 32 + row) * 64 + cp];
        }
#pragma unroll
        for (int k = 0; k < 8; k++) {                // 2048 float4
            const int idx = t + k * 256;
            *(float4*)&EB4s[idx * 4] = *(const float4*)&g_EB4[h0c * 256 + idx * 4];
        }
        __syncthreads();
#pragma unroll 4
        for (int hh = 0; hh < 32; hh++) {
            const float2 a = *(const float2*)&As[hh * 66 + 2 * k2];
            const unsigned long long arr = pack2(a.x, a.x);
            const unsigned long long aii = pack2(a.y, a.y);
#pragma unroll
            for (int j = 0; j < 8; j++) {
                const ulonglong2 e = *(const ulonglong2*)&EB4s[(hh * 64 + r * 8 + j) * 4];
                fma2(acc[j], arr, e.x);
                fma2(acc[j], aii, e.y);
            }
        }
        __syncthreads();
    }
#pragma unroll
    for (int j = 0; j < 8; j++) {
        const int k1i = r * 8 + j;
        *(float2*)&g_Xp[(size_t)((((hq * 2 + b) * 32 + c) * 64 + k1i) * 32 + k2) * 2] =
            unpack2(acc[j]);
    }
}

// Reduce 4 h-quarter partials and apply combined weights.
__global__ void k_reduce_w() {
    const int id = blockIdx.x * 256 + threadIdx.x;   // 131072
    const int k2 = id & 31, k1i = (id >> 5) & 63, c = (id >> 11) & 31, b = id >> 16;
    float xr = 0.f, xi = 0.f;
#pragma unroll
    for (int hq = 0; hq < 4; hq++) {
        const float2 p = *(const float2*)
            &g_Xp[(size_t)((((hq * 2 + b) * 32 + c) * 64 + k1i) * 32 + k2) * 2];
        xr += p.x; xi += p.y;
    }
    const int wci = ((c << 6) + k1i) * 32 + k2;
    const float wr = g_Wc[wci * 2], wi = g_Wc[wci * 2 + 1];
    const float2 o = make_float2(xr * wr - xi * wi, xr * wi + xi * wr);
    *(float2*)&g_XW[((size_t)(b * 32 + c) * 64 + k1i) * 64 + 2 * k2] = o;
}

// ---------------------------------------------------------------------------
// Stage C: Z[b,h,c,2k2] = sum_{k1i} XW[b,c,k1i,k2] * e^{+2pi i k1 h/1024}/1024.
// CTA per (hb(16h), c, b).  Thread: k2 = t&31, 2 h values.
// ---------------------------------------------------------------------------
__global__ void __launch_bounds__(256) kC() {
    const int hb = blockIdx.x, c = blockIdx.y, b = blockIdx.z;
    const int h0 = hb * 16;
    __shared__ __align__(16) float XWs[64 * 64];
    __shared__ __align__(16) float EC4s[16 * 256];
    const int t = threadIdx.x;
#pragma unroll
    for (int k = 0; k < 8; k++) {                    // 2048 float2
        const int idx = t + k * 256;
        const int row = idx >> 5, cp = (idx & 31) * 2;
        *(float2*)&XWs[row * 64 + cp] =
            *(const float2*)&g_XW[((size_t)(b * 32 + c) * 64 + row) * 64 + cp];
    }
#pragma unroll
    for (int k = 0; k < 4; k++) {                    // 1024 float4
        const int idx = t + k * 256;
        *(float4*)&EC4s[idx * 4] = *(const float4*)&g_EC4[h0 * 256 + idx * 4];
    }
    __syncthreads();
    const int k2 = t & 31, r = t >> 5;
    unsigned long long acc[2] = {};
#pragma unroll 8
    for (int k1i = 0; k1i < 64; k1i++) {
        const float2 xw = *(const float2*)&XWs[k1i * 64 + 2 * k2];
        const unsigned long long xrr = pack2(xw.x, xw.x);
        const unsigned long long xii = pack2(xw.y, xw.y);
#pragma unroll
        for (int i = 0; i < 2; i++) {
            const ulonglong2 e = *(const ulonglong2*)&EC4s[((r * 2 + i) * 64 + k1i) * 4];
            fma2(acc[i], xrr, e.x);
            fma2(acc[i], xii, e.y);
        }
    }
#pragma unroll
    for (int i = 0; i < 2; i++) {
        const int h = h0 + r * 2 + i;
        *(float2*)&g_Z[(((size_t)b * 1024 + h) * 32 + c) * 64 + 2 * k2] = unpack2(acc[i]);
    }
}

// ---------------------------------------------------------------------------
// Stage D: y[b,h,w,c] = sum_fcol GD[w,fcol] * Z[b,h,c,fcol].
// CTA per (h,b).  M=1024(w) x N=32(c) x K=64, w-chunks of 128.
// Thread: 4 w x 4 c; f32x2 packs even/odd-fcol partial sums.
// ---------------------------------------------------------------------------
__global__ void __launch_bounds__(256) kD(float* __restrict__ y) {
    const int h = blockIdx.x, b = blockIdx.y;
    __shared__ __align__(16) float Zs[32 * 66];     // [c][fcol]
    __shared__ __align__(16) float Gs[128 * 66];    // [w][fcol]
    const int t = threadIdx.x;
    const int cg = (t & 7) * 4;
    const int wg = (t >> 3) * 4;
    const float* zb = g_Z + ((size_t)(b * 1024 + h)) * 32 * 64;
#pragma unroll
    for (int k = 0; k < 4; k++) {                    // 1024 float2
        const int idx = t + k * 256;
        const int row = idx >> 5, cp = (idx & 31) * 2;
        *(float2*)&Zs[row * 66 + cp] = *(const float2*)&zb[row * 64 + cp];
    }
    float* yb = y + ((size_t)(b * 1024 + h)) * 1024 * 32;

    for (int w0 = 0; w0 < 1024; w0 += 128) {
#pragma unroll
        for (int k = 0; k < 16; k++) {               // 4096 float2
            const int idx = t + k * 256;
            const int row = idx >> 5, cp = (idx & 31) * 2;
            *(float2*)&Gs[row * 66 + cp] = *(const float2*)&g_GD[(w0 + row) * 64 + cp];
        }
        __syncthreads();
        unsigned long long acc[4][4] = {};
#pragma unroll 8
        for (int fp = 0; fp < 32; fp++) {
            unsigned long long zv[4], gv[4];
#pragma unroll
            for (int i = 0; i < 4; i++)
                zv[i] = *(const unsigned long long*)&Zs[(cg + i) * 66 + 2 * fp];
#pragma unroll
            for (int i = 0; i < 4; i++)
                gv[i] = *(const unsigned long long*)&Gs[(wg + i) * 66 + 2 * fp];
#pragma unroll
            for (int wi = 0; wi < 4; wi++)
#pragma unroll
                for (int ci = 0; ci < 4; ci++)
                    fma2(acc[wi][ci], gv[wi], zv[ci]);
        }
#pragma unroll
        for (int wi = 0; wi < 4; wi++) {
            const float2 a0 = unpack2(acc[wi][0]);
            const float2 a1 = unpack2(acc[wi][1]);
            const float2 a2 = unpack2(acc[wi][2]);
            const float2 a3 = unpack2(acc[wi][3]);
            float4 o;
            o.x = a0.x + a0.y; o.y = a1.x + a1.y;
            o.z = a2.x + a2.y; o.w = a3.x + a3.y;
            *(float4*)&yb[(size_t)(w0 + wg + wi) * 32 + cg] = o;
        }
        __syncthreads();
    }
}

// ---------------------------------------------------------------------------
extern "C" void kernel_launch(void* const* d_in, const int* in_sizes, int n_in,
                              void* d_out, int out_size) {
    const float* x   = (const float*)d_in[0];
    const float* w0r = (const float*)d_in[1];
    const float* w0i = (const float*)d_in[2];
    const float* w1r = (const float*)d_in[3];
    const float* w1i = (const float*)d_in[4];
    const float* w2r = (const float*)d_in[5];
    const float* w2i = (const float*)d_in[6];
    float* y = (float*)d_out;

    k_init_tables<<<1024, 64>>>();
    k_init_w<<<256, 256>>>(w0r, w0i, w1r, w1i, w2r, w2i);
    kA<<<dim3(1024, 2), 256>>>(x);
    kB<<<dim3(4, 32, 2), 256>>>();
    k_reduce_w<<<512, 256>>>();
    kC<<<dim3(64, 32, 2), 256>>>();
    kD<<<dim3(1024, 2), 256>>>(y);
}